// round 1
// baseline (speedup 1.0000x reference)
#include <cuda_runtime.h>

#define HS 68   // padded row stride (floats) for h / hp tiles: (4n+f)%32 conflict-free

// exp(x) for x <= 0, via 2^(x*log2e) with degree-6 Taylor on f in [-0.5,0.5].
// Rel err ~1e-7. Clamps to [-87, 0]; inputs are always <= 0 on the paths used.
__device__ __forceinline__ float fexp_(float x) {
    x = fmaxf(fminf(x, 0.0f), -87.0f);
    float y = x * 1.4426950408889634f;
    float n = rintf(y);
    float f = y - n;
    float p =       1.5403530393381608e-4f;
    p = fmaf(p, f, 1.3333558146428443e-3f);
    p = fmaf(p, f, 9.6181291076284770e-3f);
    p = fmaf(p, f, 5.5504108664821580e-2f);
    p = fmaf(p, f, 2.4022650695910070e-1f);
    p = fmaf(p, f, 6.9314718055994530e-1f);
    p = fmaf(p, f, 1.0f);
    int e = (int)n;
    return __int_as_float((e + 127) << 23) * p;
}

// Masked instance norm over the 64 rows of h[64][HS] (64 channels), in place.
// Matches: mean/var over masked rows, normalization applied to ALL rows.
__device__ __forceinline__ void inorm(float* __restrict__ h,
                                      const float* __restrict__ maskf,
                                      float* __restrict__ red,
                                      float* __restrict__ meanv,
                                      float* __restrict__ rstd,
                                      int tid) {
    int c = tid & 63, part = tid >> 6;
    float s1 = 0.f, s2 = 0.f;
    int n0 = part << 4;
    #pragma unroll 4
    for (int k = 0; k < 16; k++) {
        float m = maskf[n0 + k];
        float v = h[(n0 + k) * HS + c] * m;
        s1 += v;
        s2 = fmaf(v, v, s2);
    }
    red[(part << 6) + c] = s1;
    red[256 + (part << 6) + c] = s2;
    __syncthreads();
    if (tid < 64) {
        float cnt = 0.f;
        #pragma unroll 8
        for (int n = 0; n < 64; n++) cnt += maskf[n];
        if (cnt <= 0.f) cnt = 1.f;
        float rc = 1.0f / cnt;
        float s1t = red[tid] + red[64 + tid] + red[128 + tid] + red[192 + tid];
        float s2t = red[256 + tid] + red[320 + tid] + red[384 + tid] + red[448 + tid];
        float mn = s1t * rc;
        float var = fmaxf(s2t * rc - mn * mn, 0.f);
        meanv[tid] = mn;
        rstd[tid] = rsqrtf(var + 1e-5f);
    }
    __syncthreads();
    #pragma unroll
    for (int k = 0; k < 4; k++) {
        int i = tid + (k << 8);
        int n = i >> 4, c4 = (i & 15) << 2;
        float4 v  = *(float4*)&h[n * HS + c4];
        float4 mn = *(float4*)&meanv[c4];
        float4 rs = *(float4*)&rstd[c4];
        v.x = (v.x - mn.x) * rs.x;
        v.y = (v.y - mn.y) * rs.y;
        v.z = (v.z - mn.z) * rs.z;
        v.w = (v.w - mn.w) * rs.w;
        *(float4*)&h[n * HS + c4] = v;
    }
    __syncthreads();
}

// hp[64][64 cols, stride HS] = h[64][64] @ W[64][64]. Thread = (row, 16-col strip).
__device__ __forceinline__ void gemm64(const float* __restrict__ h,
                                       const float* __restrict__ W,
                                       float* __restrict__ hp, int tid) {
    int n = tid >> 2;
    int cg = (tid & 3) << 4;
    float acc[16];
    #pragma unroll
    for (int j = 0; j < 16; j++) acc[j] = 0.f;
    #pragma unroll 4
    for (int f = 0; f < 64; f++) {
        float hv = h[n * HS + f];
        #pragma unroll
        for (int j4 = 0; j4 < 4; j4++) {
            float4 w4 = *(const float4*)&W[(f << 6) + cg + (j4 << 2)];
            acc[j4 * 4 + 0] = fmaf(hv, w4.x, acc[j4 * 4 + 0]);
            acc[j4 * 4 + 1] = fmaf(hv, w4.y, acc[j4 * 4 + 1]);
            acc[j4 * 4 + 2] = fmaf(hv, w4.z, acc[j4 * 4 + 2]);
            acc[j4 * 4 + 3] = fmaf(hv, w4.w, acc[j4 * 4 + 3]);
        }
    }
    #pragma unroll
    for (int j4 = 0; j4 < 4; j4++) {
        float4 o = make_float4(acc[j4 * 4 + 0], acc[j4 * 4 + 1],
                               acc[j4 * 4 + 2], acc[j4 * 4 + 3]);
        *(float4*)&hp[n * HS + cg + (j4 << 2)] = o;
    }
}

__global__ __launch_bounds__(256)
void gat_kernel(const float* __restrict__ x,
                const int* __restrict__ fhi,
                const float* __restrict__ w0,
                const float* __restrict__ as0,
                const float* __restrict__ ad0,
                const float* __restrict__ b0,
                const float* __restrict__ w1,
                const float* __restrict__ as1,
                const float* __restrict__ ad1,
                const float* __restrict__ b1,
                float* __restrict__ out) {
    extern __shared__ float sm[];
    float* h     = sm;              // 64*68 = 4352
    float* hp    = sm + 4352;       // 4352
    float* W     = sm + 8704;       // 4096
    float* maskf = sm + 12800;      // 64
    float* meanv = sm + 12864;      // 64
    float* rstd  = sm + 12928;      // 64
    float* sv    = sm + 12992;      // 256
    float* dv    = sm + 13248;      // 256
    float* red   = sm + 13504;      // 512 -> total 14016 floats

    int b = blockIdx.x;
    int scene = b >> 3;       // T = 8
    int t = b & 7;
    int tid = threadIdx.x;

    // ---- load x tile, mask, W0 (W[f][h*16+o] = w0[h,f,o]) ----
    const float4* xb = (const float4*)(x + (size_t)b * 4096);
    #pragma unroll
    for (int k = 0; k < 4; k++) {
        int i = tid + (k << 8);
        int n = i >> 4, c4 = (i & 15) << 2;
        *(float4*)&h[n * HS + c4] = xb[i];
    }
    if (tid < 64)
        maskf[tid] = (fhi[(scene << 6) + tid] <= t) ? 1.0f : 0.0f;
    #pragma unroll
    for (int k = 0; k < 16; k++) {
        int i = tid + (k << 8);
        int f = i >> 6, c = i & 63;
        W[i] = w0[((c >> 4) << 10) + (f << 4) + (c & 15)];
    }
    __syncthreads();

    // ================= layer 0 (4 heads, f_out = 16) =================
    inorm(h, maskf, red, meanv, rstd, tid);
    gemm64(h, W, hp, tid);
    __syncthreads();

    { // scores: s[h][n], d[h][n]
        int hh = tid >> 6, n = tid & 63;
        float ss = 0.f, dd = 0.f;
        #pragma unroll
        for (int o = 0; o < 16; o++) {
            float v = hp[n * HS + (hh << 4) + o];
            ss = fmaf(v, as0[(hh << 4) + o], ss);
            dd = fmaf(v, ad0[(hh << 4) + o], dd);
        }
        sv[(hh << 6) + n] = ss;
        dv[(hh << 6) + n] = dd;
    }
    __syncthreads();

    { // attention row (h,n): softmax over m, aggregate hp, elu + bias -> h
        int hh = tid >> 6, n = tid & 63;
        float sn = sv[(hh << 6) + n];
        float valid = maskf[n];
        float mx = -1e30f;
        #pragma unroll 4
        for (int m = 0; m < 64; m++) {
            if (maskf[m] > 0.f) {
                float v = sn + dv[(hh << 6) + m];
                v = fmaxf(v, 0.2f * v);
                mx = fmaxf(mx, v);
            }
        }
        float acc[16];
        #pragma unroll
        for (int j = 0; j < 16; j++) acc[j] = 0.f;
        float psum = 0.f;
        #pragma unroll 2
        for (int m = 0; m < 64; m++) {
            float v = sn + dv[(hh << 6) + m];
            v = fmaxf(v, 0.2f * v);
            float p = (maskf[m] > 0.f) ? fexp_(v - mx) : 0.f;
            p = (valid > 0.f) ? p : 1.0f;   // fully-masked row -> uniform
            psum += p;
            const float* hpr = &hp[m * HS + (hh << 4)];
            #pragma unroll
            for (int j4 = 0; j4 < 4; j4++) {
                float4 w4 = *(const float4*)&hpr[j4 << 2];
                acc[j4 * 4 + 0] = fmaf(p, w4.x, acc[j4 * 4 + 0]);
                acc[j4 * 4 + 1] = fmaf(p, w4.y, acc[j4 * 4 + 1]);
                acc[j4 * 4 + 2] = fmaf(p, w4.z, acc[j4 * 4 + 2]);
                acc[j4 * 4 + 3] = fmaf(p, w4.w, acc[j4 * 4 + 3]);
            }
        }
        float inv = 1.0f / psum;
        #pragma unroll
        for (int j4 = 0; j4 < 4; j4++) {
            float4 o;
            float e0 = fmaf(acc[j4 * 4 + 0], inv, b0[j4 * 4 + 0]);
            float e1 = fmaf(acc[j4 * 4 + 1], inv, b0[j4 * 4 + 1]);
            float e2 = fmaf(acc[j4 * 4 + 2], inv, b0[j4 * 4 + 2]);
            float e3 = fmaf(acc[j4 * 4 + 3], inv, b0[j4 * 4 + 3]);
            o.x = (e0 > 0.f) ? e0 : (fexp_(e0) - 1.0f);   // ELU
            o.y = (e1 > 0.f) ? e1 : (fexp_(e1) - 1.0f);
            o.z = (e2 > 0.f) ? e2 : (fexp_(e2) - 1.0f);
            o.w = (e3 > 0.f) ? e3 : (fexp_(e3) - 1.0f);
            *(float4*)&h[n * HS + (hh << 4) + (j4 << 2)] = o;
        }
    }
    // load W1 (w1 is already [f_in=64][f_out=64])
    #pragma unroll
    for (int k = 0; k < 16; k++) {
        int i = tid + (k << 8);
        W[i] = w1[i];
    }
    __syncthreads();

    // ================= layer 1 (1 head, f_out = 64) =================
    inorm(h, maskf, red, meanv, rstd, tid);
    gemm64(h, W, hp, tid);
    __syncthreads();

    if (tid < 64) { // scores
        float ss = 0.f, dd = 0.f;
        #pragma unroll 4
        for (int o = 0; o < 64; o++) {
            float v = hp[tid * HS + o];
            ss = fmaf(v, as1[o], ss);
            dd = fmaf(v, ad1[o], dd);
        }
        sv[tid] = ss;
        dv[tid] = dd;
    }
    __syncthreads();

    { // attention: thread = (row n, 16-col strip og); write result to gmem
        int n = tid >> 2, og = (tid & 3) << 4;
        float sn = sv[n];
        float valid = maskf[n];
        float mx = -1e30f;
        #pragma unroll 4
        for (int m = 0; m < 64; m++) {
            if (maskf[m] > 0.f) {
                float v = sn + dv[m];
                v = fmaxf(v, 0.2f * v);
                mx = fmaxf(mx, v);
            }
        }
        float acc[16];
        #pragma unroll
        for (int j = 0; j < 16; j++) acc[j] = 0.f;
        float psum = 0.f;
        #pragma unroll 2
        for (int m = 0; m < 64; m++) {
            float v = sn + dv[m];
            v = fmaxf(v, 0.2f * v);
            float p = (maskf[m] > 0.f) ? fexp_(v - mx) : 0.f;
            p = (valid > 0.f) ? p : 1.0f;
            psum += p;
            const float* hpr = &hp[m * HS + og];
            #pragma unroll
            for (int j4 = 0; j4 < 4; j4++) {
                float4 w4 = *(const float4*)&hpr[j4 << 2];
                acc[j4 * 4 + 0] = fmaf(p, w4.x, acc[j4 * 4 + 0]);
                acc[j4 * 4 + 1] = fmaf(p, w4.y, acc[j4 * 4 + 1]);
                acc[j4 * 4 + 2] = fmaf(p, w4.z, acc[j4 * 4 + 2]);
                acc[j4 * 4 + 3] = fmaf(p, w4.w, acc[j4 * 4 + 3]);
            }
        }
        float inv = 1.0f / psum;
        float* ob = out + (size_t)b * 4096 + (n << 6) + og;
        #pragma unroll
        for (int j4 = 0; j4 < 4; j4++) {
            float4 o;
            o.x = fmaf(acc[j4 * 4 + 0], inv, b1[og + j4 * 4 + 0]);
            o.y = fmaf(acc[j4 * 4 + 1], inv, b1[og + j4 * 4 + 1]);
            o.z = fmaf(acc[j4 * 4 + 2], inv, b1[og + j4 * 4 + 2]);
            o.w = fmaf(acc[j4 * 4 + 3], inv, b1[og + j4 * 4 + 3]);
            *(float4*)&ob[j4 << 2] = o;
        }
    }
}

extern "C" void kernel_launch(void* const* d_in, const int* in_sizes, int n_in,
                              void* d_out, int out_size) {
    const float* x   = (const float*)d_in[0];
    const int*   fhi = (const int*)d_in[1];
    const float* w0  = (const float*)d_in[2];
    const float* as0 = (const float*)d_in[3];
    const float* ad0 = (const float*)d_in[4];
    const float* b0  = (const float*)d_in[5];
    const float* w1  = (const float*)d_in[6];
    const float* as1 = (const float*)d_in[7];
    const float* ad1 = (const float*)d_in[8];
    const float* b1  = (const float*)d_in[9];
    float* out = (float*)d_out;

    const int smem = 14016 * 4;  // 56064 bytes dynamic shared
    cudaFuncSetAttribute(gat_kernel, cudaFuncAttributeMaxDynamicSharedMemorySize, smem);
    gat_kernel<<<8192, 256, smem>>>(x, fhi, w0, as0, ad0, b0, w1, as1, ad1, b1, out);
}

// round 2
// speedup vs baseline: 1.0008x; 1.0008x over previous
#include <cuda_runtime.h>

#define HS 68   // padded row stride (floats) for h / hp tiles: (4n+f)%32 conflict-free

// exp(x) for x <= 0, via 2^(x*log2e) with degree-6 Taylor on f in [-0.5,0.5].
// Rel err ~1e-7. Clamps to [-87, 0]; inputs are always <= 0 on the paths used.
__device__ __forceinline__ float fexp_(float x) {
    x = fmaxf(fminf(x, 0.0f), -87.0f);
    float y = x * 1.4426950408889634f;
    float n = rintf(y);
    float f = y - n;
    float p =       1.5403530393381608e-4f;
    p = fmaf(p, f, 1.3333558146428443e-3f);
    p = fmaf(p, f, 9.6181291076284770e-3f);
    p = fmaf(p, f, 5.5504108664821580e-2f);
    p = fmaf(p, f, 2.4022650695910070e-1f);
    p = fmaf(p, f, 6.9314718055994530e-1f);
    p = fmaf(p, f, 1.0f);
    int e = (int)n;
    return __int_as_float((e + 127) << 23) * p;
}

// Masked instance norm over the 64 rows of h[64][HS] (64 channels), in place.
// Matches: mean/var over masked rows, normalization applied to ALL rows.
__device__ __forceinline__ void inorm(float* __restrict__ h,
                                      const float* __restrict__ maskf,
                                      float* __restrict__ red,
                                      float* __restrict__ meanv,
                                      float* __restrict__ rstd,
                                      int tid) {
    int c = tid & 63, part = tid >> 6;
    float s1 = 0.f, s2 = 0.f;
    int n0 = part << 4;
    #pragma unroll 4
    for (int k = 0; k < 16; k++) {
        float m = maskf[n0 + k];
        float v = h[(n0 + k) * HS + c] * m;
        s1 += v;
        s2 = fmaf(v, v, s2);
    }
    red[(part << 6) + c] = s1;
    red[256 + (part << 6) + c] = s2;
    __syncthreads();
    if (tid < 64) {
        float cnt = 0.f;
        #pragma unroll 8
        for (int n = 0; n < 64; n++) cnt += maskf[n];
        if (cnt <= 0.f) cnt = 1.f;
        float rc = 1.0f / cnt;
        float s1t = red[tid] + red[64 + tid] + red[128 + tid] + red[192 + tid];
        float s2t = red[256 + tid] + red[320 + tid] + red[384 + tid] + red[448 + tid];
        float mn = s1t * rc;
        float var = fmaxf(s2t * rc - mn * mn, 0.f);
        meanv[tid] = mn;
        rstd[tid] = rsqrtf(var + 1e-5f);
    }
    __syncthreads();
    #pragma unroll
    for (int k = 0; k < 4; k++) {
        int i = tid + (k << 8);
        int n = i >> 4, c4 = (i & 15) << 2;
        float4 v  = *(float4*)&h[n * HS + c4];
        float4 mn = *(float4*)&meanv[c4];
        float4 rs = *(float4*)&rstd[c4];
        v.x = (v.x - mn.x) * rs.x;
        v.y = (v.y - mn.y) * rs.y;
        v.z = (v.z - mn.z) * rs.z;
        v.w = (v.w - mn.w) * rs.w;
        *(float4*)&h[n * HS + c4] = v;
    }
    __syncthreads();
}

// hp[64][64 cols, stride HS] = h[64][64] @ W[64][64]. Thread = (row, 16-col strip).
__device__ __forceinline__ void gemm64(const float* __restrict__ h,
                                       const float* __restrict__ W,
                                       float* __restrict__ hp, int tid) {
    int n = tid >> 2;
    int cg = (tid & 3) << 4;
    float acc[16];
    #pragma unroll
    for (int j = 0; j < 16; j++) acc[j] = 0.f;
    #pragma unroll 4
    for (int f = 0; f < 64; f++) {
        float hv = h[n * HS + f];
        #pragma unroll
        for (int j4 = 0; j4 < 4; j4++) {
            float4 w4 = *(const float4*)&W[(f << 6) + cg + (j4 << 2)];
            acc[j4 * 4 + 0] = fmaf(hv, w4.x, acc[j4 * 4 + 0]);
            acc[j4 * 4 + 1] = fmaf(hv, w4.y, acc[j4 * 4 + 1]);
            acc[j4 * 4 + 2] = fmaf(hv, w4.z, acc[j4 * 4 + 2]);
            acc[j4 * 4 + 3] = fmaf(hv, w4.w, acc[j4 * 4 + 3]);
        }
    }
    #pragma unroll
    for (int j4 = 0; j4 < 4; j4++) {
        float4 o = make_float4(acc[j4 * 4 + 0], acc[j4 * 4 + 1],
                               acc[j4 * 4 + 2], acc[j4 * 4 + 3]);
        *(float4*)&hp[n * HS + cg + (j4 << 2)] = o;
    }
}

__global__ __launch_bounds__(256)
void gat_kernel(const float* __restrict__ x,
                const int* __restrict__ fhi,
                const float* __restrict__ w0,
                const float* __restrict__ as0,
                const float* __restrict__ ad0,
                const float* __restrict__ b0,
                const float* __restrict__ w1,
                const float* __restrict__ as1,
                const float* __restrict__ ad1,
                const float* __restrict__ b1,
                float* __restrict__ out) {
    extern __shared__ float sm[];
    float* h     = sm;              // 64*68 = 4352
    float* hp    = sm + 4352;       // 4352
    float* W     = sm + 8704;       // 4096
    float* maskf = sm + 12800;      // 64
    float* meanv = sm + 12864;      // 64
    float* rstd  = sm + 12928;      // 64
    float* sv    = sm + 12992;      // 256
    float* dv    = sm + 13248;      // 256
    float* red   = sm + 13504;      // 512 -> total 14016 floats

    int b = blockIdx.x;
    int scene = b >> 3;       // T = 8
    int t = b & 7;
    int tid = threadIdx.x;

    // ---- load x tile, mask, W0 (W[f][h*16+o] = w0[h,f,o]) ----
    const float4* xb = (const float4*)(x + (size_t)b * 4096);
    #pragma unroll
    for (int k = 0; k < 4; k++) {
        int i = tid + (k << 8);
        int n = i >> 4, c4 = (i & 15) << 2;
        *(float4*)&h[n * HS + c4] = xb[i];
    }
    if (tid < 64)
        maskf[tid] = (fhi[(scene << 6) + tid] <= t) ? 1.0f : 0.0f;
    #pragma unroll
    for (int k = 0; k < 16; k++) {
        int i = tid + (k << 8);
        int f = i >> 6, c = i & 63;
        W[i] = w0[((c >> 4) << 10) + (f << 4) + (c & 15)];
    }
    __syncthreads();

    // ================= layer 0 (4 heads, f_out = 16) =================
    inorm(h, maskf, red, meanv, rstd, tid);
    gemm64(h, W, hp, tid);
    __syncthreads();

    { // scores: s[h][n], d[h][n]
        int hh = tid >> 6, n = tid & 63;
        float ss = 0.f, dd = 0.f;
        #pragma unroll
        for (int o = 0; o < 16; o++) {
            float v = hp[n * HS + (hh << 4) + o];
            ss = fmaf(v, as0[(hh << 4) + o], ss);
            dd = fmaf(v, ad0[(hh << 4) + o], dd);
        }
        sv[(hh << 6) + n] = ss;
        dv[(hh << 6) + n] = dd;
    }
    __syncthreads();

    { // attention row (h,n): softmax over m, aggregate hp, elu + bias -> h
        int hh = tid >> 6, n = tid & 63;
        float sn = sv[(hh << 6) + n];
        float valid = maskf[n];
        float mx = -1e30f;
        #pragma unroll 4
        for (int m = 0; m < 64; m++) {
            if (maskf[m] > 0.f) {
                float v = sn + dv[(hh << 6) + m];
                v = fmaxf(v, 0.2f * v);
                mx = fmaxf(mx, v);
            }
        }
        float acc[16];
        #pragma unroll
        for (int j = 0; j < 16; j++) acc[j] = 0.f;
        float psum = 0.f;
        #pragma unroll 2
        for (int m = 0; m < 64; m++) {
            float v = sn + dv[(hh << 6) + m];
            v = fmaxf(v, 0.2f * v);
            float p = (maskf[m] > 0.f) ? fexp_(v - mx) : 0.f;
            p = (valid > 0.f) ? p : 1.0f;   // fully-masked row -> uniform
            psum += p;
            const float* hpr = &hp[m * HS + (hh << 4)];
            #pragma unroll
            for (int j4 = 0; j4 < 4; j4++) {
                float4 w4 = *(const float4*)&hpr[j4 << 2];
                acc[j4 * 4 + 0] = fmaf(p, w4.x, acc[j4 * 4 + 0]);
                acc[j4 * 4 + 1] = fmaf(p, w4.y, acc[j4 * 4 + 1]);
                acc[j4 * 4 + 2] = fmaf(p, w4.z, acc[j4 * 4 + 2]);
                acc[j4 * 4 + 3] = fmaf(p, w4.w, acc[j4 * 4 + 3]);
            }
        }
        float inv = 1.0f / psum;
        #pragma unroll
        for (int j4 = 0; j4 < 4; j4++) {
            float4 o;
            float e0 = fmaf(acc[j4 * 4 + 0], inv, b0[j4 * 4 + 0]);
            float e1 = fmaf(acc[j4 * 4 + 1], inv, b0[j4 * 4 + 1]);
            float e2 = fmaf(acc[j4 * 4 + 2], inv, b0[j4 * 4 + 2]);
            float e3 = fmaf(acc[j4 * 4 + 3], inv, b0[j4 * 4 + 3]);
            o.x = (e0 > 0.f) ? e0 : (fexp_(e0) - 1.0f);   // ELU
            o.y = (e1 > 0.f) ? e1 : (fexp_(e1) - 1.0f);
            o.z = (e2 > 0.f) ? e2 : (fexp_(e2) - 1.0f);
            o.w = (e3 > 0.f) ? e3 : (fexp_(e3) - 1.0f);
            *(float4*)&h[n * HS + (hh << 4) + (j4 << 2)] = o;
        }
    }
    // load W1 (w1 is already [f_in=64][f_out=64])
    #pragma unroll
    for (int k = 0; k < 16; k++) {
        int i = tid + (k << 8);
        W[i] = w1[i];
    }
    __syncthreads();

    // ================= layer 1 (1 head, f_out = 64) =================
    inorm(h, maskf, red, meanv, rstd, tid);
    gemm64(h, W, hp, tid);
    __syncthreads();

    if (tid < 64) { // scores
        float ss = 0.f, dd = 0.f;
        #pragma unroll 4
        for (int o = 0; o < 64; o++) {
            float v = hp[tid * HS + o];
            ss = fmaf(v, as1[o], ss);
            dd = fmaf(v, ad1[o], dd);
        }
        sv[tid] = ss;
        dv[tid] = dd;
    }
    __syncthreads();

    { // attention: thread = (row n, 16-col strip og); write result to gmem
        int n = tid >> 2, og = (tid & 3) << 4;
        float sn = sv[n];
        float valid = maskf[n];
        float mx = -1e30f;
        #pragma unroll 4
        for (int m = 0; m < 64; m++) {
            if (maskf[m] > 0.f) {
                float v = sn + dv[m];
                v = fmaxf(v, 0.2f * v);
                mx = fmaxf(mx, v);
            }
        }
        float acc[16];
        #pragma unroll
        for (int j = 0; j < 16; j++) acc[j] = 0.f;
        float psum = 0.f;
        #pragma unroll 2
        for (int m = 0; m < 64; m++) {
            float v = sn + dv[m];
            v = fmaxf(v, 0.2f * v);
            float p = (maskf[m] > 0.f) ? fexp_(v - mx) : 0.f;
            p = (valid > 0.f) ? p : 1.0f;
            psum += p;
            const float* hpr = &hp[m * HS + og];
            #pragma unroll
            for (int j4 = 0; j4 < 4; j4++) {
                float4 w4 = *(const float4*)&hpr[j4 << 2];
                acc[j4 * 4 + 0] = fmaf(p, w4.x, acc[j4 * 4 + 0]);
                acc[j4 * 4 + 1] = fmaf(p, w4.y, acc[j4 * 4 + 1]);
                acc[j4 * 4 + 2] = fmaf(p, w4.z, acc[j4 * 4 + 2]);
                acc[j4 * 4 + 3] = fmaf(p, w4.w, acc[j4 * 4 + 3]);
            }
        }
        float inv = 1.0f / psum;
        float* ob = out + (size_t)b * 4096 + (n << 6) + og;
        #pragma unroll
        for (int j4 = 0; j4 < 4; j4++) {
            float4 o;
            o.x = fmaf(acc[j4 * 4 + 0], inv, b1[og + j4 * 4 + 0]);
            o.y = fmaf(acc[j4 * 4 + 1], inv, b1[og + j4 * 4 + 1]);
            o.z = fmaf(acc[j4 * 4 + 2], inv, b1[og + j4 * 4 + 2]);
            o.w = fmaf(acc[j4 * 4 + 3], inv, b1[og + j4 * 4 + 3]);
            *(float4*)&ob[j4 << 2] = o;
        }
    }
}

extern "C" void kernel_launch(void* const* d_in, const int* in_sizes, int n_in,
                              void* d_out, int out_size) {
    const float* x   = (const float*)d_in[0];
    const int*   fhi = (const int*)d_in[1];
    const float* w0  = (const float*)d_in[2];
    const float* as0 = (const float*)d_in[3];
    const float* ad0 = (const float*)d_in[4];
    const float* b0  = (const float*)d_in[5];
    const float* w1  = (const float*)d_in[6];
    const float* as1 = (const float*)d_in[7];
    const float* ad1 = (const float*)d_in[8];
    const float* b1  = (const float*)d_in[9];
    float* out = (float*)d_out;

    const int smem = 14016 * 4;  // 56064 bytes dynamic shared
    cudaFuncSetAttribute(gat_kernel, cudaFuncAttributeMaxDynamicSharedMemorySize, smem);
    gat_kernel<<<8192, 256, smem>>>(x, fhi, w0, as0, ad0, b0, w1, as1, ad1, b1, out);
}

// round 3
// speedup vs baseline: 2.3561x; 2.3542x over previous
#include <cuda_runtime.h>

// ---------------- shared memory layout (float offsets) ----------------
#define H_    0        // h tile 64x64 swizzled          (4096)
#define HP_   4096     // hp tile 64x64 swizzled         (4096)
#define RG_   8192     // W (4096) / p heads (4*4112)    (16448)
#define PHSTR 4112
#define SV_   24640    // (256)
#define DV_   24896    // (256)
#define RED_  25152    // (512)
#define DMX_  25664    // (16)
#define MSK_  25680    // (64)
#define MEAN_ 25744    // (64)
#define RSTD_ 25808    // (64)
#define INVP_ 25872    // (288) L0: head*68+n ; L1: [n]
#define AV_   26160    // (256) as0|ad0|as1|ad1
#define BIA_  26416    // (80)  b0[16] | b1[64]
#define SMF   26496    // total floats -> 105984 bytes

#define FMA4(acc, s, wv) do { \
    acc.x = fmaf((s), (wv).x, acc.x); \
    acc.y = fmaf((s), (wv).y, acc.y); \
    acc.z = fmaf((s), (wv).z, acc.z); \
    acc.w = fmaf((s), (wv).w, acc.w); } while (0)

// exp(x) for x <= 0 (clamped), FMA-pipe only, rel err ~1e-7
__device__ __forceinline__ float fexp_(float x) {
    x = fmaxf(fminf(x, 0.0f), -87.0f);
    float y = x * 1.4426950408889634f;
    float n = rintf(y);
    float f = y - n;
    float p =       1.5403530393381608e-4f;
    p = fmaf(p, f, 1.3333558146428443e-3f);
    p = fmaf(p, f, 9.6181291076284770e-3f);
    p = fmaf(p, f, 5.5504108664821580e-2f);
    p = fmaf(p, f, 2.4022650695910070e-1f);
    p = fmaf(p, f, 6.9314718055994530e-1f);
    p = fmaf(p, f, 1.0f);
    return __int_as_float(((int)n + 127) << 23) * p;
}

// masked instance norm over swizzled h[64x64], column-parallel (conflict-free)
__device__ __forceinline__ void inorm(float* __restrict__ sm, int tid) {
    int c = tid & 63, part = tid >> 6, n0 = part << 4;
    int chi = (c >> 2), clo = (c & 3);
    float s1 = 0.f, s2 = 0.f;
    #pragma unroll
    for (int k = 0; k < 16; k++) {
        int n = n0 + k;
        int ad = (n << 6) + (((chi ^ (n >> 2)) & 15) << 2) + clo;
        float v = sm[H_ + ad] * sm[MSK_ + n];
        s1 += v; s2 = fmaf(v, v, s2);
    }
    sm[RED_ + (part << 6) + c] = s1;
    sm[RED_ + 256 + (part << 6) + c] = s2;
    __syncthreads();
    if (tid < 64) {
        float cnt = 0.f;
        #pragma unroll 8
        for (int n = 0; n < 64; n++) cnt += sm[MSK_ + n];
        if (cnt <= 0.f) cnt = 1.f;
        float rc = 1.0f / cnt;
        float a = sm[RED_ + tid] + sm[RED_ + 64 + tid] + sm[RED_ + 128 + tid] + sm[RED_ + 192 + tid];
        float q = sm[RED_ + 256 + tid] + sm[RED_ + 320 + tid] + sm[RED_ + 384 + tid] + sm[RED_ + 448 + tid];
        float mn = a * rc;
        float var = fmaxf(q * rc - mn * mn, 0.f);
        sm[MEAN_ + tid] = mn;
        sm[RSTD_ + tid] = rsqrtf(var + 1e-5f);
    }
    __syncthreads();
    float mn = sm[MEAN_ + c], rs = sm[RSTD_ + c];
    #pragma unroll
    for (int k = 0; k < 16; k++) {
        int n = n0 + k;
        int ad = H_ + (n << 6) + (((chi ^ (n >> 2)) & 15) << 2) + clo;
        sm[ad] = (sm[ad] - mn) * rs;
    }
    __syncthreads();
}

// hp(swizzled) = h(swizzled) @ W(plain [64][64]); 4x4 register tile
__device__ __forceinline__ void gemmW(float* __restrict__ sm, int tid) {
    int lane = tid & 31, w = tid >> 5;
    int nt = ((w >> 1) << 2) | (lane >> 3);   // 0..15 row tile
    int ct = ((w & 1) << 3) | (lane & 7);     // 0..15 col tile
    int n0 = nt << 2, c0 = ct << 2;
    float4 A0 = {0,0,0,0}, A1 = A0, A2 = A0, A3 = A0;
    #pragma unroll
    for (int fb = 0; fb < 16; fb++) {
        int uo = ((fb ^ nt) & 15) << 2;
        float4 a0 = *(const float4*)&sm[H_ + ((n0 + 0) << 6) + uo];
        float4 a1 = *(const float4*)&sm[H_ + ((n0 + 1) << 6) + uo];
        float4 a2 = *(const float4*)&sm[H_ + ((n0 + 2) << 6) + uo];
        float4 a3 = *(const float4*)&sm[H_ + ((n0 + 3) << 6) + uo];
        const float* wb = &sm[RG_ + (fb << 8) + c0];
        float4 b0 = *(const float4*)&wb[0];
        float4 b1 = *(const float4*)&wb[64];
        float4 b2 = *(const float4*)&wb[128];
        float4 b3 = *(const float4*)&wb[192];
        FMA4(A0, a0.x, b0); FMA4(A0, a0.y, b1); FMA4(A0, a0.z, b2); FMA4(A0, a0.w, b3);
        FMA4(A1, a1.x, b0); FMA4(A1, a1.y, b1); FMA4(A1, a1.z, b2); FMA4(A1, a1.w, b3);
        FMA4(A2, a2.x, b0); FMA4(A2, a2.y, b1); FMA4(A2, a2.z, b2); FMA4(A2, a2.w, b3);
        FMA4(A3, a3.x, b0); FMA4(A3, a3.y, b1); FMA4(A3, a3.z, b2); FMA4(A3, a3.w, b3);
    }
    int so = ((ct ^ nt) & 15) << 2;
    *(float4*)&sm[HP_ + ((n0 + 0) << 6) + so] = A0;
    *(float4*)&sm[HP_ + ((n0 + 1) << 6) + so] = A1;
    *(float4*)&sm[HP_ + ((n0 + 2) << 6) + so] = A2;
    *(float4*)&sm[HP_ + ((n0 + 3) << 6) + so] = A3;
}

// out = (p @ hp) * invp + bias [+ ELU];  A = p (per-head swizzled), B = hp swizzled
__device__ __forceinline__ void aggregate(float* __restrict__ sm, int tid, int layer,
                                          float* __restrict__ gout) {
    int lane = tid & 31, w = tid >> 5;
    int nt = ((w >> 1) << 2) | (lane >> 3);
    int ct = ((w & 1) << 3) | (lane & 7);
    int n0 = nt << 2, c0 = ct << 2;
    int head = (layer == 0) ? (ct >> 2) : 0;
    const float* A = &sm[RG_ + head * PHSTR];
    float4 A0 = {0,0,0,0}, A1 = A0, A2 = A0, A3 = A0;
    #pragma unroll
    for (int fb = 0; fb < 16; fb++) {
        int uo = ((fb ^ nt) & 15) << 2;
        float4 a0 = *(const float4*)&A[((n0 + 0) << 6) + uo];
        float4 a1 = *(const float4*)&A[((n0 + 1) << 6) + uo];
        float4 a2 = *(const float4*)&A[((n0 + 2) << 6) + uo];
        float4 a3 = *(const float4*)&A[((n0 + 3) << 6) + uo];
        int vo = ((ct ^ fb) & 15) << 2;
        const float* hb = &sm[HP_ + (fb << 8)];
        float4 b0 = *(const float4*)&hb[vo];
        float4 b1 = *(const float4*)&hb[64 + vo];
        float4 b2 = *(const float4*)&hb[128 + vo];
        float4 b3 = *(const float4*)&hb[192 + vo];
        FMA4(A0, a0.x, b0); FMA4(A0, a0.y, b1); FMA4(A0, a0.z, b2); FMA4(A0, a0.w, b3);
        FMA4(A1, a1.x, b0); FMA4(A1, a1.y, b1); FMA4(A1, a1.z, b2); FMA4(A1, a1.w, b3);
        FMA4(A2, a2.x, b0); FMA4(A2, a2.y, b1); FMA4(A2, a2.z, b2); FMA4(A2, a2.w, b3);
        FMA4(A3, a3.x, b0); FMA4(A3, a3.y, b1); FMA4(A3, a3.z, b2); FMA4(A3, a3.w, b3);
    }
    if (layer == 0) {
        float4 bias = *(const float4*)&sm[BIA_ + ((ct & 3) << 2)];
        int so = ((ct ^ nt) & 15) << 2;
        float4 accs[4] = {A0, A1, A2, A3};
        #pragma unroll
        for (int r = 0; r < 4; r++) {
            float iv = sm[INVP_ + head * 68 + n0 + r];
            float4 e;
            e.x = fmaf(accs[r].x, iv, bias.x);
            e.y = fmaf(accs[r].y, iv, bias.y);
            e.z = fmaf(accs[r].z, iv, bias.z);
            e.w = fmaf(accs[r].w, iv, bias.w);
            e.x = (e.x > 0.f) ? e.x : (fexp_(e.x) - 1.0f);
            e.y = (e.y > 0.f) ? e.y : (fexp_(e.y) - 1.0f);
            e.z = (e.z > 0.f) ? e.z : (fexp_(e.z) - 1.0f);
            e.w = (e.w > 0.f) ? e.w : (fexp_(e.w) - 1.0f);
            *(float4*)&sm[H_ + ((n0 + r) << 6) + so] = e;
        }
    } else {
        float4 bias = *(const float4*)&sm[BIA_ + 16 + c0];
        float4 accs[4] = {A0, A1, A2, A3};
        #pragma unroll
        for (int r = 0; r < 4; r++) {
            float iv = sm[INVP_ + n0 + r];
            float4 e;
            e.x = fmaf(accs[r].x, iv, bias.x);
            e.y = fmaf(accs[r].y, iv, bias.y);
            e.z = fmaf(accs[r].z, iv, bias.z);
            e.w = fmaf(accs[r].w, iv, bias.w);
            *(float4*)&gout[((n0 + r) << 6) + c0] = e;
        }
    }
}

__global__ __launch_bounds__(256, 2)
void gat_kernel(const float* __restrict__ x,
                const int* __restrict__ fhi,
                const float* __restrict__ w0,
                const float* __restrict__ as0,
                const float* __restrict__ ad0,
                const float* __restrict__ b0,
                const float* __restrict__ w1,
                const float* __restrict__ as1,
                const float* __restrict__ ad1,
                const float* __restrict__ b1,
                float* __restrict__ out) {
    extern __shared__ float sm[];
    int b = blockIdx.x;
    int scene = b >> 3, t = b & 7;
    int tid = threadIdx.x;
    int lane = tid & 31;

    // ---- global loads: x (swizzled), mask, W0 (plain), a-vecs, biases ----
    {
        const float4* xb = (const float4*)(x + (size_t)b * 4096);
        #pragma unroll
        for (int k = 0; k < 4; k++) {
            int i = tid + (k << 8);
            int n = i >> 4, chunk = i & 15;
            *(float4*)&sm[H_ + (n << 6) + (((chunk ^ (n >> 2)) & 15) << 2)] = xb[i];
        }
        if (tid < 64) {
            sm[MSK_ + tid] = (fhi[(scene << 6) + tid] <= t) ? 1.0f : 0.0f;
            sm[AV_ + tid]       = as0[tid];
            sm[AV_ + 64 + tid]  = ad0[tid];
            sm[AV_ + 128 + tid] = as1[tid];
            sm[AV_ + 192 + tid] = ad1[tid];
            sm[BIA_ + 16 + tid] = b1[tid];
            if (tid < 16) sm[BIA_ + tid] = b0[tid];
        }
        #pragma unroll
        for (int k = 0; k < 16; k++) {
            int i = tid + (k << 8);
            int f = i >> 6, c = i & 63;
            sm[RG_ + i] = w0[((c >> 4) << 10) + (f << 4) + (c & 15)];
        }
    }
    __syncthreads();

    // ================= layer 0 =================
    inorm(sm, tid);
    gemmW(sm, tid);
    __syncthreads();

    { // scores s,d per (head hh, node n) + per-warp masked d-max
        int hh = tid >> 6, n = tid & 63, a = n >> 2;
        float s = 0.f, d = 0.f;
        #pragma unroll
        for (int j = 0; j < 4; j++) {
            int jj = (j + n) & 3;
            int chunk = (hh << 2) + jj;
            float4 v = *(const float4*)&sm[HP_ + (n << 6) + (((chunk ^ a) & 15) << 2)];
            float4 vs = *(const float4*)&sm[AV_ + (hh << 4) + (jj << 2)];
            float4 vd = *(const float4*)&sm[AV_ + 64 + (hh << 4) + (jj << 2)];
            s = fmaf(v.x, vs.x, fmaf(v.y, vs.y, fmaf(v.z, vs.z, fmaf(v.w, vs.w, s))));
            d = fmaf(v.x, vd.x, fmaf(v.y, vd.y, fmaf(v.z, vd.z, fmaf(v.w, vd.w, d))));
        }
        sm[SV_ + tid] = s;
        sm[DV_ + tid] = d;
        float md = (sm[MSK_ + n] > 0.f) ? d : -1e30f;
        #pragma unroll
        for (int off = 16; off > 0; off >>= 1)
            md = fmaxf(md, __shfl_xor_sync(0xffffffffu, md, off));
        if (lane == 0) sm[DMX_ + (tid >> 5)] = md;
    }
    __syncthreads();

    { // p-pass L0: thread = (head, row); one exp per entry; conflict-free stores
        int hh = tid >> 6, n = tid & 63, a = n >> 2;
        float sB = sm[SV_ + tid];
        float valid = sm[MSK_ + n];
        float dmx = fmaxf(sm[DMX_ + (hh << 1)], sm[DMX_ + (hh << 1) + 1]);
        float mxv = sB + dmx; mxv = fmaxf(mxv, 0.2f * mxv);
        float psum = 0.f;
        float* pb = &sm[RG_ + hh * PHSTR + (n << 6)];
        int rot = (n & 3) << 1;
        #pragma unroll 4
        for (int i = 0; i < 16; i++) {
            int sg = (i + rot) & 15;
            float4 d4 = *(const float4*)&sm[DV_ + (hh << 6) + (sg << 2)];
            float4 m4 = *(const float4*)&sm[MSK_ + (sg << 2)];
            float4 pv;
            float v;
            v = sB + d4.x; v = fmaxf(v, 0.2f * v);
            pv.x = (m4.x > 0.f) ? fexp_(v - mxv) : 0.f; pv.x = (valid > 0.f) ? pv.x : 1.0f;
            v = sB + d4.y; v = fmaxf(v, 0.2f * v);
            pv.y = (m4.y > 0.f) ? fexp_(v - mxv) : 0.f; pv.y = (valid > 0.f) ? pv.y : 1.0f;
            v = sB + d4.z; v = fmaxf(v, 0.2f * v);
            pv.z = (m4.z > 0.f) ? fexp_(v - mxv) : 0.f; pv.z = (valid > 0.f) ? pv.z : 1.0f;
            v = sB + d4.w; v = fmaxf(v, 0.2f * v);
            pv.w = (m4.w > 0.f) ? fexp_(v - mxv) : 0.f; pv.w = (valid > 0.f) ? pv.w : 1.0f;
            psum += (pv.x + pv.y) + (pv.z + pv.w);
            *(float4*)&pb[((sg ^ a) & 15) << 2] = pv;
        }
        sm[INVP_ + hh * 68 + n] = 1.0f / psum;
    }
    __syncthreads();

    aggregate(sm, tid, 0, (float*)0);   // writes ELU(out0)+b0 into h
    __syncthreads();

    // load W1 (overwrites dead p region)
    #pragma unroll
    for (int k = 0; k < 16; k++) {
        int i = tid + (k << 8);
        sm[RG_ + i] = w1[i];
    }
    __syncthreads();

    // ================= layer 1 =================
    inorm(sm, tid);
    gemmW(sm, tid);
    __syncthreads();

    { // scores L1, seg-split partial dots
        int row = tid & 63, seg = tid >> 6, a = row >> 2;
        float s = 0.f, d = 0.f;
        #pragma unroll
        for (int j = 0; j < 4; j++) {
            int jj = (j + row) & 3;
            int chunk = (seg << 2) + jj;
            float4 v = *(const float4*)&sm[HP_ + (row << 6) + (((chunk ^ a) & 15) << 2)];
            float4 vs = *(const float4*)&sm[AV_ + 128 + (seg << 4) + (jj << 2)];
            float4 vd = *(const float4*)&sm[AV_ + 192 + (seg << 4) + (jj << 2)];
            s = fmaf(v.x, vs.x, fmaf(v.y, vs.y, fmaf(v.z, vs.z, fmaf(v.w, vs.w, s))));
            d = fmaf(v.x, vd.x, fmaf(v.y, vd.y, fmaf(v.z, vd.z, fmaf(v.w, vd.w, d))));
        }
        sm[RED_ + tid] = s;
        sm[RED_ + 256 + tid] = d;
    }
    __syncthreads();
    if (tid < 64) {
        float s = sm[RED_ + tid] + sm[RED_ + 64 + tid] + sm[RED_ + 128 + tid] + sm[RED_ + 192 + tid];
        float d = sm[RED_ + 256 + tid] + sm[RED_ + 320 + tid] + sm[RED_ + 384 + tid] + sm[RED_ + 448 + tid];
        sm[SV_ + tid] = s;
        sm[DV_ + tid] = d;
        float md = (sm[MSK_ + tid] > 0.f) ? d : -1e30f;
        #pragma unroll
        for (int off = 16; off > 0; off >>= 1)
            md = fmaxf(md, __shfl_xor_sync(0xffffffffu, md, off));
        if (lane == 0) sm[DMX_ + 8 + (tid >> 5)] = md;
    }
    __syncthreads();

    { // p-pass L1: thread = (row, 16-m segment)
        int row = tid & 63, seg = tid >> 6, a = row >> 2;
        float sB = sm[SV_ + row];
        float valid = sm[MSK_ + row];
        float dmx = fmaxf(sm[DMX_ + 8], sm[DMX_ + 9]);
        float mxv = sB + dmx; mxv = fmaxf(mxv, 0.2f * mxv);
        float psum = 0.f;
        float* pb = &sm[RG_ + (row << 6)];
        #pragma unroll
        for (int i = 0; i < 4; i++) {
            int jj = (i + row) & 3;
            int sg = (seg << 2) + jj;
            float4 d4 = *(const float4*)&sm[DV_ + (sg << 2)];
            float4 m4 = *(const float4*)&sm[MSK_ + (sg << 2)];
            float4 pv;
            float v;
            v = sB + d4.x; v = fmaxf(v, 0.2f * v);
            pv.x = (m4.x > 0.f) ? fexp_(v - mxv) : 0.f; pv.x = (valid > 0.f) ? pv.x : 1.0f;
            v = sB + d4.y; v = fmaxf(v, 0.2f * v);
            pv.y = (m4.y > 0.f) ? fexp_(v - mxv) : 0.f; pv.y = (valid > 0.f) ? pv.y : 1.0f;
            v = sB + d4.z; v = fmaxf(v, 0.2f * v);
            pv.z = (m4.z > 0.f) ? fexp_(v - mxv) : 0.f; pv.z = (valid > 0.f) ? pv.z : 1.0f;
            v = sB + d4.w; v = fmaxf(v, 0.2f * v);
            pv.w = (m4.w > 0.f) ? fexp_(v - mxv) : 0.f; pv.w = (valid > 0.f) ? pv.w : 1.0f;
            psum += (pv.x + pv.y) + (pv.z + pv.w);
            *(float4*)&pb[((sg ^ a) & 15) << 2] = pv;
        }
        sm[RED_ + tid] = psum;
    }
    __syncthreads();
    if (tid < 64)
        sm[INVP_ + tid] = 1.0f / (sm[RED_ + tid] + sm[RED_ + 64 + tid] +
                                  sm[RED_ + 128 + tid] + sm[RED_ + 192 + tid]);
    __syncthreads();

    aggregate(sm, tid, 1, out + (size_t)b * 4096);
}

extern "C" void kernel_launch(void* const* d_in, const int* in_sizes, int n_in,
                              void* d_out, int out_size) {
    const float* x   = (const float*)d_in[0];
    const int*   fhi = (const int*)d_in[1];
    const float* w0  = (const float*)d_in[2];
    const float* as0 = (const float*)d_in[3];
    const float* ad0 = (const float*)d_in[4];
    const float* b0  = (const float*)d_in[5];
    const float* w1  = (const float*)d_in[6];
    const float* as1 = (const float*)d_in[7];
    const float* ad1 = (const float*)d_in[8];
    const float* b1  = (const float*)d_in[9];
    float* out = (float*)d_out;

    const int smem = SMF * 4;   // 105984 bytes
    cudaFuncSetAttribute(gat_kernel, cudaFuncAttributeMaxDynamicSharedMemorySize, smem);
    gat_kernel<<<8192, 256, smem>>>(x, fhi, w0, as0, ad0, b0, w1, as1, ad1, b1, out);
}

// round 4
// speedup vs baseline: 3.0294x; 1.2858x over previous
#include <cuda_runtime.h>
#include <cuda_fp16.h>

// ---------------- shared memory layout (float/word offsets) ----------------
#define H_    0        // h tile 64x64 swizzled (4096)
#define HP_   4096     // hp tile 64x64 swizzled (4096)
#define RG_   8192     // union: W [4096 floats] | p fp16 [4 heads x 2052 words] (8224)
#define PHW   2052     // p head stride in 32-bit words
#define SV_   16416    // 256
#define DV_   16672    // 256 (masked d: d_m or -3e38)
#define RED_  16928    // 512
#define DMX_  17440    // 16
#define MSK_  17456    // 64
#define MEAN_ 17520    // 64
#define RSTD_ 17584    // 64
#define INVP_ 17648    // 288 (L0: head*68+n ; L1: [n])
#define AV_   17936    // 256 (as0|ad0|as1|ad1)
#define BIA_  18192    // 80  (b0[16] | b1[64])
#define SMF   18272    // 73088 bytes

#define L2E 1.4426950408889634f

#define FMA4(acc, s, wv) do { \
    acc.x = fmaf((s), (wv).x, acc.x); \
    acc.y = fmaf((s), (wv).y, acc.y); \
    acc.z = fmaf((s), (wv).z, acc.z); \
    acc.w = fmaf((s), (wv).w, acc.w); } while (0)

__device__ __forceinline__ float ex2_(float x) {
    float r; asm("ex2.approx.f32 %0, %1;" : "=f"(r) : "f"(x)); return r;
}

// masked instance norm over swizzled h[64x64], column-parallel (conflict-free)
__device__ __forceinline__ void inorm(float* __restrict__ sm, int tid) {
    int c = tid & 63, part = tid >> 6, n0 = part << 4;
    int chi = (c >> 2), clo = (c & 3);
    float s1 = 0.f, s2 = 0.f;
    #pragma unroll
    for (int k = 0; k < 16; k++) {
        int n = n0 + k;
        int ad = (n << 6) + (((chi ^ (n >> 2)) & 15) << 2) + clo;
        float v = sm[H_ + ad] * sm[MSK_ + n];
        s1 += v; s2 = fmaf(v, v, s2);
    }
    sm[RED_ + (part << 6) + c] = s1;
    sm[RED_ + 256 + (part << 6) + c] = s2;
    __syncthreads();
    if (tid < 64) {
        float cnt = 0.f;
        #pragma unroll 8
        for (int n = 0; n < 64; n++) cnt += sm[MSK_ + n];
        if (cnt <= 0.f) cnt = 1.f;
        float rc = 1.0f / cnt;
        float a = sm[RED_ + tid] + sm[RED_ + 64 + tid] + sm[RED_ + 128 + tid] + sm[RED_ + 192 + tid];
        float q = sm[RED_ + 256 + tid] + sm[RED_ + 320 + tid] + sm[RED_ + 384 + tid] + sm[RED_ + 448 + tid];
        float mn = a * rc;
        float var = fmaxf(q * rc - mn * mn, 0.f);
        sm[MEAN_ + tid] = mn;
        sm[RSTD_ + tid] = rsqrtf(var + 1e-5f);
    }
    __syncthreads();
    float mn = sm[MEAN_ + c], rs = sm[RSTD_ + c];
    #pragma unroll
    for (int k = 0; k < 16; k++) {
        int n = n0 + k;
        int ad = H_ + (n << 6) + (((chi ^ (n >> 2)) & 15) << 2) + clo;
        sm[ad] = (sm[ad] - mn) * rs;
    }
    __syncthreads();
}

// hp(swizzled) = h(swizzled) @ W(plain [64][64]); 4x4 tile, A rows sequential
__device__ __forceinline__ void gemmW(float* __restrict__ sm, int tid) {
    int lane = tid & 31, w = tid >> 5;
    int nt = ((w >> 1) << 2) | (lane >> 3);
    int ct = ((w & 1) << 3) | (lane & 7);
    int n0 = nt << 2, c0 = ct << 2;
    float4 A0 = {0,0,0,0}, A1 = A0, A2 = A0, A3 = A0;
    #pragma unroll
    for (int fb = 0; fb < 16; fb++) {
        int uo = ((fb ^ nt) & 15) << 2;
        const float* wb = &sm[RG_ + (fb << 8) + c0];
        float4 b0 = *(const float4*)&wb[0];
        float4 b1 = *(const float4*)&wb[64];
        float4 b2 = *(const float4*)&wb[128];
        float4 b3 = *(const float4*)&wb[192];
        float4 a;
        a = *(const float4*)&sm[H_ + ((n0 + 0) << 6) + uo];
        FMA4(A0, a.x, b0); FMA4(A0, a.y, b1); FMA4(A0, a.z, b2); FMA4(A0, a.w, b3);
        a = *(const float4*)&sm[H_ + ((n0 + 1) << 6) + uo];
        FMA4(A1, a.x, b0); FMA4(A1, a.y, b1); FMA4(A1, a.z, b2); FMA4(A1, a.w, b3);
        a = *(const float4*)&sm[H_ + ((n0 + 2) << 6) + uo];
        FMA4(A2, a.x, b0); FMA4(A2, a.y, b1); FMA4(A2, a.z, b2); FMA4(A2, a.w, b3);
        a = *(const float4*)&sm[H_ + ((n0 + 3) << 6) + uo];
        FMA4(A3, a.x, b0); FMA4(A3, a.y, b1); FMA4(A3, a.z, b2); FMA4(A3, a.w, b3);
    }
    int so = ((ct ^ nt) & 15) << 2;
    *(float4*)&sm[HP_ + ((n0 + 0) << 6) + so] = A0;
    *(float4*)&sm[HP_ + ((n0 + 1) << 6) + so] = A1;
    *(float4*)&sm[HP_ + ((n0 + 2) << 6) + so] = A2;
    *(float4*)&sm[HP_ + ((n0 + 3) << 6) + so] = A3;
}

// out = (p_fp16 @ hp) * invp + bias [+ ELU]
__device__ __forceinline__ void aggregate(float* __restrict__ sm,
                                          const unsigned* __restrict__ smu,
                                          int tid, int layer,
                                          float* __restrict__ gout) {
    int lane = tid & 31, w = tid >> 5;
    int nt = ((w >> 1) << 2) | (lane >> 3);
    int ct = ((w & 1) << 3) | (lane & 7);
    int n0 = nt << 2, c0 = ct << 2;
    int head = (layer == 0) ? (ct >> 2) : 0;
    int swm = (layer == 0) ? 15 : 12;
    const unsigned* A = smu + RG_ + head * PHW;
    float4 A0 = {0,0,0,0}, A1 = A0, A2 = A0, A3 = A0;
    #pragma unroll
    for (int fb = 0; fb < 16; fb++) {
        const float* hb = &sm[HP_ + (fb << 8)];
        int vo = ((ct ^ fb) & 15) << 2;
        float4 b0 = *(const float4*)&hb[vo];
        float4 b1 = *(const float4*)&hb[64 + vo];
        float4 b2 = *(const float4*)&hb[128 + vo];
        float4 b3 = *(const float4*)&hb[192 + vo];
        uint2 av; float2 f01, f23;
        av = *(const uint2*)(A + ((n0 + 0) << 5) + (((fb ^ ((n0 + 0) & swm)) & 15) << 1));
        f01 = __half22float2(*(__half2*)&av.x); f23 = __half22float2(*(__half2*)&av.y);
        FMA4(A0, f01.x, b0); FMA4(A0, f01.y, b1); FMA4(A0, f23.x, b2); FMA4(A0, f23.y, b3);
        av = *(const uint2*)(A + ((n0 + 1) << 5) + (((fb ^ ((n0 + 1) & swm)) & 15) << 1));
        f01 = __half22float2(*(__half2*)&av.x); f23 = __half22float2(*(__half2*)&av.y);
        FMA4(A1, f01.x, b0); FMA4(A1, f01.y, b1); FMA4(A1, f23.x, b2); FMA4(A1, f23.y, b3);
        av = *(const uint2*)(A + ((n0 + 2) << 5) + (((fb ^ ((n0 + 2) & swm)) & 15) << 1));
        f01 = __half22float2(*(__half2*)&av.x); f23 = __half22float2(*(__half2*)&av.y);
        FMA4(A2, f01.x, b0); FMA4(A2, f01.y, b1); FMA4(A2, f23.x, b2); FMA4(A2, f23.y, b3);
        av = *(const uint2*)(A + ((n0 + 3) << 5) + (((fb ^ ((n0 + 3) & swm)) & 15) << 1));
        f01 = __half22float2(*(__half2*)&av.x); f23 = __half22float2(*(__half2*)&av.y);
        FMA4(A3, f01.x, b0); FMA4(A3, f01.y, b1); FMA4(A3, f23.x, b2); FMA4(A3, f23.y, b3);
    }
    if (layer == 0) {
        float4 bias = *(const float4*)&sm[BIA_ + ((ct & 3) << 2)];
        int so = ((ct ^ nt) & 15) << 2;
        float4 accs[4] = {A0, A1, A2, A3};
        #pragma unroll
        for (int r = 0; r < 4; r++) {
            float iv = sm[INVP_ + head * 68 + n0 + r];
            float4 e;
            e.x = fmaf(accs[r].x, iv, bias.x);
            e.y = fmaf(accs[r].y, iv, bias.y);
            e.z = fmaf(accs[r].z, iv, bias.z);
            e.w = fmaf(accs[r].w, iv, bias.w);
            e.x = (e.x > 0.f) ? e.x : (ex2_(e.x * L2E) - 1.0f);
            e.y = (e.y > 0.f) ? e.y : (ex2_(e.y * L2E) - 1.0f);
            e.z = (e.z > 0.f) ? e.z : (ex2_(e.z * L2E) - 1.0f);
            e.w = (e.w > 0.f) ? e.w : (ex2_(e.w * L2E) - 1.0f);
            *(float4*)&sm[H_ + ((n0 + r) << 6) + so] = e;
        }
    } else {
        float4 bias = *(const float4*)&sm[BIA_ + 16 + c0];
        float4 accs[4] = {A0, A1, A2, A3};
        #pragma unroll
        for (int r = 0; r < 4; r++) {
            float iv = sm[INVP_ + n0 + r];
            float4 e;
            e.x = fmaf(accs[r].x, iv, bias.x);
            e.y = fmaf(accs[r].y, iv, bias.y);
            e.z = fmaf(accs[r].z, iv, bias.z);
            e.w = fmaf(accs[r].w, iv, bias.w);
            *(float4*)&gout[((n0 + r) << 6) + c0] = e;
        }
    }
}

__global__ __launch_bounds__(256, 3)
void gat_kernel(const float* __restrict__ x,
                const int* __restrict__ fhi,
                const float* __restrict__ w0,
                const float* __restrict__ as0,
                const float* __restrict__ ad0,
                const float* __restrict__ b0,
                const float* __restrict__ w1,
                const float* __restrict__ as1,
                const float* __restrict__ ad1,
                const float* __restrict__ b1,
                float* __restrict__ out) {
    extern __shared__ float sm[];
    unsigned* smu = (unsigned*)sm;
    int b = blockIdx.x;
    int scene = b >> 3, t = b & 7;
    int tid = threadIdx.x;
    int lane = tid & 31;

    // ---- global loads ----
    {
        const float4* xb = (const float4*)(x + (size_t)b * 4096);
        #pragma unroll
        for (int k = 0; k < 4; k++) {
            int i = tid + (k << 8);
            int n = i >> 4, chunk = i & 15;
            *(float4*)&sm[H_ + (n << 6) + (((chunk ^ (n >> 2)) & 15) << 2)] = xb[i];
        }
        if (tid < 64) {
            sm[MSK_ + tid] = (fhi[(scene << 6) + tid] <= t) ? 1.0f : 0.0f;
            sm[AV_ + tid]       = as0[tid];
            sm[AV_ + 64 + tid]  = ad0[tid];
            sm[AV_ + 128 + tid] = as1[tid];
            sm[AV_ + 192 + tid] = ad1[tid];
            sm[BIA_ + 16 + tid] = b1[tid];
            if (tid < 16) sm[BIA_ + tid] = b0[tid];
        }
        #pragma unroll
        for (int k = 0; k < 16; k++) {
            int i = tid + (k << 8);
            int f = i >> 6, c = i & 63;
            sm[RG_ + i] = w0[((c >> 4) << 10) + (f << 4) + (c & 15)];
        }
    }
    __syncthreads();

    // ================= layer 0 =================
    inorm(sm, tid);
    gemmW(sm, tid);
    __syncthreads();

    { // scores: s,d per (head, node); DV holds masked d; per-warp max
        int hh = tid >> 6, n = tid & 63, a = n >> 2;
        float s = 0.f, d = 0.f;
        #pragma unroll
        for (int j = 0; j < 4; j++) {
            int jj = (j + n) & 3;
            int chunk = (hh << 2) + jj;
            float4 v = *(const float4*)&sm[HP_ + (n << 6) + (((chunk ^ a) & 15) << 2)];
            float4 vs = *(const float4*)&sm[AV_ + (hh << 4) + (jj << 2)];
            float4 vd = *(const float4*)&sm[AV_ + 64 + (hh << 4) + (jj << 2)];
            s = fmaf(v.x, vs.x, fmaf(v.y, vs.y, fmaf(v.z, vs.z, fmaf(v.w, vs.w, s))));
            d = fmaf(v.x, vd.x, fmaf(v.y, vd.y, fmaf(v.z, vd.z, fmaf(v.w, vd.w, d))));
        }
        sm[SV_ + tid] = s;
        float dm = (sm[MSK_ + n] > 0.f) ? d : -3.0e38f;
        sm[DV_ + tid] = dm;
        float md = dm;
        #pragma unroll
        for (int off = 16; off > 0; off >>= 1)
            md = fmaxf(md, __shfl_xor_sync(0xffffffffu, md, off));
        if (lane == 0) sm[DMX_ + (tid >> 5)] = md;
    }
    __syncthreads();

    { // p-pass L0: thread = (head, row); MUFU exp; fp16 stores
        int hh = tid >> 6, n = tid & 63;
        float sB = sm[SV_ + tid];
        float valid = sm[MSK_ + n];
        float dmx = fmaxf(sm[DMX_ + (hh << 1)], sm[DMX_ + (hh << 1) + 1]);
        float mxv = sB + dmx; mxv = fmaxf(mxv, 0.2f * mxv);
        float nml = -mxv * L2E;
        float psum = 0.f;
        unsigned* pb = smu + RG_ + hh * PHW + (n << 5);
        int nx = n & 15;
        const float* dvb = &sm[DV_ + (hh << 6)];
        #pragma unroll 4
        for (int c = 0; c < 16; c++) {
            float4 d4 = *(const float4*)&dvb[c << 2];
            float v, lr;
            float4 pv;
            v = sB + d4.x; lr = fmaxf(v, 0.2f * v); pv.x = ex2_(fmaf(lr, L2E, nml));
            v = sB + d4.y; lr = fmaxf(v, 0.2f * v); pv.y = ex2_(fmaf(lr, L2E, nml));
            v = sB + d4.z; lr = fmaxf(v, 0.2f * v); pv.z = ex2_(fmaf(lr, L2E, nml));
            v = sB + d4.w; lr = fmaxf(v, 0.2f * v); pv.w = ex2_(fmaf(lr, L2E, nml));
            if (valid <= 0.f) { pv.x = 1.f; pv.y = 1.f; pv.z = 1.f; pv.w = 1.f; }
            psum += (pv.x + pv.y) + (pv.z + pv.w);
            __half2 h01 = __floats2half2_rn(pv.x, pv.y);
            __half2 h23 = __floats2half2_rn(pv.z, pv.w);
            uint2 uu;
            uu.x = *(unsigned*)&h01;
            uu.y = *(unsigned*)&h23;
            *(uint2*)(pb + ((c ^ nx) << 1)) = uu;
        }
        sm[INVP_ + hh * 68 + n] = 1.0f / psum;
    }
    __syncthreads();

    aggregate(sm, smu, tid, 0, (float*)0);   // ELU(out0)+b0 -> h
    __syncthreads();

    // load W1 (overwrites dead p region)
    #pragma unroll
    for (int k = 0; k < 16; k++) {
        int i = tid + (k << 8);
        sm[RG_ + i] = w1[i];
    }
    __syncthreads();

    // ================= layer 1 =================
    inorm(sm, tid);
    gemmW(sm, tid);
    __syncthreads();

    { // scores L1: seg-split partial dots
        int row = tid & 63, seg = tid >> 6, a = row >> 2;
        float s = 0.f, d = 0.f;
        #pragma unroll
        for (int j = 0; j < 4; j++) {
            int jj = (j + row) & 3;
            int chunk = (seg << 2) + jj;
            float4 v = *(const float4*)&sm[HP_ + (row << 6) + (((chunk ^ a) & 15) << 2)];
            float4 vs = *(const float4*)&sm[AV_ + 128 + (seg << 4) + (jj << 2)];
            float4 vd = *(const float4*)&sm[AV_ + 192 + (seg << 4) + (jj << 2)];
            s = fmaf(v.x, vs.x, fmaf(v.y, vs.y, fmaf(v.z, vs.z, fmaf(v.w, vs.w, s))));
            d = fmaf(v.x, vd.x, fmaf(v.y, vd.y, fmaf(v.z, vd.z, fmaf(v.w, vd.w, d))));
        }
        sm[RED_ + tid] = s;
        sm[RED_ + 256 + tid] = d;
    }
    __syncthreads();
    if (tid < 64) {
        float s = sm[RED_ + tid] + sm[RED_ + 64 + tid] + sm[RED_ + 128 + tid] + sm[RED_ + 192 + tid];
        float d = sm[RED_ + 256 + tid] + sm[RED_ + 320 + tid] + sm[RED_ + 384 + tid] + sm[RED_ + 448 + tid];
        sm[SV_ + tid] = s;
        float dm = (sm[MSK_ + tid] > 0.f) ? d : -3.0e38f;
        sm[DV_ + tid] = dm;
        float md = dm;
        #pragma unroll
        for (int off = 16; off > 0; off >>= 1)
            md = fmaxf(md, __shfl_xor_sync(0xffffffffu, md, off));
        if (lane == 0) sm[DMX_ + 8 + (tid >> 5)] = md;
    }
    __syncthreads();

    { // p-pass L1: thread = (row, 16-m segment); fp16 stores
        int row = tid & 63, seg = tid >> 6;
        float sB = sm[SV_ + row];
        float valid = sm[MSK_ + row];
        float dmx = fmaxf(sm[DMX_ + 8], sm[DMX_ + 9]);
        float mxv = sB + dmx; mxv = fmaxf(mxv, 0.2f * mxv);
        float nml = -mxv * L2E;
        float psum = 0.f;
        unsigned* pb = smu + RG_ + (row << 5);
        int nx = row & 12;
        #pragma unroll
        for (int i = 0; i < 4; i++) {
            int jj = (i + row) & 3;
            int sg = (seg << 2) + jj;
            float4 d4 = *(const float4*)&sm[DV_ + (sg << 2)];
            float v, lr;
            float4 pv;
            v = sB + d4.x; lr = fmaxf(v, 0.2f * v); pv.x = ex2_(fmaf(lr, L2E, nml));
            v = sB + d4.y; lr = fmaxf(v, 0.2f * v); pv.y = ex2_(fmaf(lr, L2E, nml));
            v = sB + d4.z; lr = fmaxf(v, 0.2f * v); pv.z = ex2_(fmaf(lr, L2E, nml));
            v = sB + d4.w; lr = fmaxf(v, 0.2f * v); pv.w = ex2_(fmaf(lr, L2E, nml));
            if (valid <= 0.f) { pv.x = 1.f; pv.y = 1.f; pv.z = 1.f; pv.w = 1.f; }
            psum += (pv.x + pv.y) + (pv.z + pv.w);
            __half2 h01 = __floats2half2_rn(pv.x, pv.y);
            __half2 h23 = __floats2half2_rn(pv.z, pv.w);
            uint2 uu;
            uu.x = *(unsigned*)&h01;
            uu.y = *(unsigned*)&h23;
            *(uint2*)(pb + (((sg ^ nx) & 15) << 1)) = uu;
        }
        sm[RED_ + tid] = psum;
    }
    __syncthreads();
    if (tid < 64)
        sm[INVP_ + tid] = 1.0f / (sm[RED_ + tid] + sm[RED_ + 64 + tid] +
                                  sm[RED_ + 128 + tid] + sm[RED_ + 192 + tid]);
    __syncthreads();

    aggregate(sm, smu, tid, 1, out + (size_t)b * 4096);
}

extern "C" void kernel_launch(void* const* d_in, const int* in_sizes, int n_in,
                              void* d_out, int out_size) {
    const float* x   = (const float*)d_in[0];
    const int*   fhi = (const int*)d_in[1];
    const float* w0  = (const float*)d_in[2];
    const float* as0 = (const float*)d_in[3];
    const float* ad0 = (const float*)d_in[4];
    const float* b0  = (const float*)d_in[5];
    const float* w1  = (const float*)d_in[6];
    const float* as1 = (const float*)d_in[7];
    const float* ad1 = (const float*)d_in[8];
    const float* b1  = (const float*)d_in[9];
    float* out = (float*)d_out;

    const int smem = SMF * 4;   // 73088 bytes
    cudaFuncSetAttribute(gat_kernel, cudaFuncAttributeMaxDynamicSharedMemorySize, smem);
    gat_kernel<<<8192, 256, smem>>>(x, fhi, w0, as0, ad0, b0, w1, as1, ad1, b1, out);
}

// round 13
// speedup vs baseline: 3.2581x; 1.0755x over previous
#include <cuda_runtime.h>
#include <cuda_fp16.h>

// ---------------- shared memory word offsets (fp32 indexing) ----------------
#define H_    0        // h tile 64x64 fp32, XOR swizzle (4096)
#define HP_   4096     // hp tile 64x64 fp32, XOR swizzle (4096)
#define RG_   8192     // union: W [4096 floats] | p fp16 [4 heads x 2052 words] (8224)
#define PHW   2052     // p head stride in 32-bit words
#define SV_   16416    // 256
#define DV_   16672    // 256 (masked d: d_m or -3e38)
#define RED_  16928    // 512
#define DMX_  17440    // 16
#define MSK_  17456    // 64
#define MEAN_ 17520    // 64
#define RSTD_ 17584    // 64
#define INVP_ 17648    // 288 (L0: head*68+n ; L1: [n])
#define AV_   17936    // 256 (as0|ad0|as1|ad1)
#define BIA_  18192    // 80  (b0[16] | b1[64])
#define SMF   18272    // 73088 bytes

#define L2E 1.4426950408889634f

typedef unsigned long long u64t;

__device__ __forceinline__ float ex2_(float x) {
    float r; asm("ex2.approx.f32 %0, %1;" : "=f"(r) : "f"(x)); return r;
}
__device__ __forceinline__ unsigned pk2(float a, float b) {
    __half2 t = __floats2half2_rn(a, b); return *(unsigned*)&t;
}
// packed fp32x2 helpers (Blackwell FFMA2 path; bit-identical fp32 lanes)
__device__ __forceinline__ u64t dup2(float x) {
    u64t r; unsigned u = __float_as_uint(x);
    asm("mov.b64 %0, {%1, %2};" : "=l"(r) : "r"(u), "r"(u));
    return r;
}
__device__ __forceinline__ u64t fma2(u64t a, u64t b, u64t c) {
    u64t d;
    asm("fma.rn.f32x2 %0, %1, %2, %3;" : "=l"(d) : "l"(a), "l"(b), "l"(c));
    return d;
}
__device__ __forceinline__ float2 upk2(u64t v) {
    unsigned lo, hi;
    asm("mov.b64 {%0, %1}, %2;" : "=r"(lo), "=r"(hi) : "l"(v));
    return make_float2(__uint_as_float(lo), __uint_as_float(hi));
}

// masked instance norm over XOR-swizzled fp32 h[64x64], column-parallel (R4 verbatim)
__device__ __forceinline__ void inorm(float* __restrict__ sm, int tid) {
    int c = tid & 63, part = tid >> 6, n0 = part << 4;
    int chi = (c >> 2), clo = (c & 3);
    float s1 = 0.f, s2 = 0.f;
    #pragma unroll
    for (int k = 0; k < 16; k++) {
        int n = n0 + k;
        int ad = (n << 6) + (((chi ^ (n >> 2)) & 15) << 2) + clo;
        float v = sm[H_ + ad] * sm[MSK_ + n];
        s1 += v; s2 = fmaf(v, v, s2);
    }
    sm[RED_ + (part << 6) + c] = s1;
    sm[RED_ + 256 + (part << 6) + c] = s2;
    __syncthreads();
    if (tid < 64) {
        float cnt = 0.f;
        #pragma unroll 8
        for (int n = 0; n < 64; n++) cnt += sm[MSK_ + n];
        if (cnt <= 0.f) cnt = 1.f;
        float rc = 1.0f / cnt;
        float a = sm[RED_ + tid] + sm[RED_ + 64 + tid] + sm[RED_ + 128 + tid] + sm[RED_ + 192 + tid];
        float q = sm[RED_ + 256 + tid] + sm[RED_ + 320 + tid] + sm[RED_ + 384 + tid] + sm[RED_ + 448 + tid];
        float mn = a * rc;
        float var = fmaxf(q * rc - mn * mn, 0.f);
        sm[MEAN_ + tid] = mn;
        sm[RSTD_ + tid] = rsqrtf(var + 1e-5f);
    }
    __syncthreads();
    float mn = sm[MEAN_ + c], rs = sm[RSTD_ + c];
    #pragma unroll
    for (int k = 0; k < 16; k++) {
        int n = n0 + k;
        int ad = H_ + (n << 6) + (((chi ^ (n >> 2)) & 15) << 2) + clo;
        sm[ad] = (sm[ad] - mn) * rs;
    }
    __syncthreads();
}

// hp(swizzled) = h(swizzled) @ W(plain [64][64]); 4x4 tile, FFMA2 inner loops
__device__ __forceinline__ void gemmW(float* __restrict__ sm, int tid) {
    int lane = tid & 31, w = tid >> 5;
    int nt = ((w >> 1) << 2) | (lane >> 3);
    int ct = ((w & 1) << 3) | (lane & 7);
    int n0 = nt << 2, c0 = ct << 2;
    u64t A0l = 0, A0h = 0, A1l = 0, A1h = 0, A2l = 0, A2h = 0, A3l = 0, A3h = 0;
    #pragma unroll
    for (int fb = 0; fb < 16; fb++) {
        int uo = ((fb ^ nt) & 15) << 2;
        const char* wb = (const char*)&sm[RG_ + (fb << 8) + c0];
        ulonglong2 b0 = *(const ulonglong2*)(wb);
        ulonglong2 b1 = *(const ulonglong2*)(wb + 256);
        ulonglong2 b2 = *(const ulonglong2*)(wb + 512);
        ulonglong2 b3 = *(const ulonglong2*)(wb + 768);
        float4 a; u64t s;
        a = *(const float4*)&sm[H_ + ((n0 + 0) << 6) + uo];
        s = dup2(a.x); A0l = fma2(s, b0.x, A0l); A0h = fma2(s, b0.y, A0h);
        s = dup2(a.y); A0l = fma2(s, b1.x, A0l); A0h = fma2(s, b1.y, A0h);
        s = dup2(a.z); A0l = fma2(s, b2.x, A0l); A0h = fma2(s, b2.y, A0h);
        s = dup2(a.w); A0l = fma2(s, b3.x, A0l); A0h = fma2(s, b3.y, A0h);
        a = *(const float4*)&sm[H_ + ((n0 + 1) << 6) + uo];
        s = dup2(a.x); A1l = fma2(s, b0.x, A1l); A1h = fma2(s, b0.y, A1h);
        s = dup2(a.y); A1l = fma2(s, b1.x, A1l); A1h = fma2(s, b1.y, A1h);
        s = dup2(a.z); A1l = fma2(s, b2.x, A1l); A1h = fma2(s, b2.y, A1h);
        s = dup2(a.w); A1l = fma2(s, b3.x, A1l); A1h = fma2(s, b3.y, A1h);
        a = *(const float4*)&sm[H_ + ((n0 + 2) << 6) + uo];
        s = dup2(a.x); A2l = fma2(s, b0.x, A2l); A2h = fma2(s, b0.y, A2h);
        s = dup2(a.y); A2l = fma2(s, b1.x, A2l); A2h = fma2(s, b1.y, A2h);
        s = dup2(a.z); A2l = fma2(s, b2.x, A2l); A2h = fma2(s, b2.y, A2h);
        s = dup2(a.w); A2l = fma2(s, b3.x, A2l); A2h = fma2(s, b3.y, A2h);
        a = *(const float4*)&sm[H_ + ((n0 + 3) << 6) + uo];
        s = dup2(a.x); A3l = fma2(s, b0.x, A3l); A3h = fma2(s, b0.y, A3h);
        s = dup2(a.y); A3l = fma2(s, b1.x, A3l); A3h = fma2(s, b1.y, A3h);
        s = dup2(a.z); A3l = fma2(s, b2.x, A3l); A3h = fma2(s, b2.y, A3h);
        s = dup2(a.w); A3l = fma2(s, b3.x, A3l); A3h = fma2(s, b3.y, A3h);
    }
    int so = ((ct ^ nt) & 15) << 2;
    ulonglong2 st;
    st.x = A0l; st.y = A0h; *(ulonglong2*)&sm[HP_ + ((n0 + 0) << 6) + so] = st;
    st.x = A1l; st.y = A1h; *(ulonglong2*)&sm[HP_ + ((n0 + 1) << 6) + so] = st;
    st.x = A2l; st.y = A2h; *(ulonglong2*)&sm[HP_ + ((n0 + 2) << 6) + so] = st;
    st.x = A3l; st.y = A3h; *(ulonglong2*)&sm[HP_ + ((n0 + 3) << 6) + so] = st;
}

// out = (p_fp16 @ hp_fp32) * invp + bias [+ ELU]; FFMA2 inner loops (R4 layout)
__device__ __forceinline__ void aggregate(float* __restrict__ sm,
                                          const unsigned* __restrict__ smu,
                                          int tid, int layer,
                                          float* __restrict__ gout) {
    int lane = tid & 31, w = tid >> 5;
    int nt = ((w >> 1) << 2) | (lane >> 3);
    int ct = ((w & 1) << 3) | (lane & 7);
    int n0 = nt << 2, c0 = ct << 2;
    int head = (layer == 0) ? (ct >> 2) : 0;
    int swm = (layer == 0) ? 15 : 12;
    const unsigned* A = smu + RG_ + head * PHW;
    u64t acl[4] = {0, 0, 0, 0}, ach[4] = {0, 0, 0, 0};
    #pragma unroll
    for (int fb = 0; fb < 16; fb++) {
        int vo = ((ct ^ fb) & 15) << 2;
        const char* hb = (const char*)&sm[HP_ + (fb << 8) + vo];
        ulonglong2 b0 = *(const ulonglong2*)(hb);
        ulonglong2 b1 = *(const ulonglong2*)(hb + 256);
        ulonglong2 b2 = *(const ulonglong2*)(hb + 512);
        ulonglong2 b3 = *(const ulonglong2*)(hb + 768);
        #pragma unroll
        for (int r = 0; r < 4; r++) {
            int n = n0 + r;
            uint2 av = *(const uint2*)(A + (n << 5) + (((fb ^ (n & swm)) & 15) << 1));
            float2 f01 = __half22float2(*(__half2*)&av.x);
            float2 f23 = __half22float2(*(__half2*)&av.y);
            u64t s;
            s = dup2(f01.x); acl[r] = fma2(s, b0.x, acl[r]); ach[r] = fma2(s, b0.y, ach[r]);
            s = dup2(f01.y); acl[r] = fma2(s, b1.x, acl[r]); ach[r] = fma2(s, b1.y, ach[r]);
            s = dup2(f23.x); acl[r] = fma2(s, b2.x, acl[r]); ach[r] = fma2(s, b2.y, ach[r]);
            s = dup2(f23.y); acl[r] = fma2(s, b3.x, acl[r]); ach[r] = fma2(s, b3.y, ach[r]);
        }
    }
    if (layer == 0) {
        float4 bias = *(const float4*)&sm[BIA_ + ((ct & 3) << 2)];
        int so = ((ct ^ nt) & 15) << 2;
        #pragma unroll
        for (int r = 0; r < 4; r++) {
            float iv = sm[INVP_ + head * 68 + n0 + r];
            float2 lo = upk2(acl[r]), hi = upk2(ach[r]);
            float4 e;
            e.x = fmaf(lo.x, iv, bias.x);
            e.y = fmaf(lo.y, iv, bias.y);
            e.z = fmaf(hi.x, iv, bias.z);
            e.w = fmaf(hi.y, iv, bias.w);
            e.x = (e.x > 0.f) ? e.x : (ex2_(e.x * L2E) - 1.0f);
            e.y = (e.y > 0.f) ? e.y : (ex2_(e.y * L2E) - 1.0f);
            e.z = (e.z > 0.f) ? e.z : (ex2_(e.z * L2E) - 1.0f);
            e.w = (e.w > 0.f) ? e.w : (ex2_(e.w * L2E) - 1.0f);
            *(float4*)&sm[H_ + ((n0 + r) << 6) + so] = e;
        }
    } else {
        float4 bias = *(const float4*)&sm[BIA_ + 16 + c0];
        #pragma unroll
        for (int r = 0; r < 4; r++) {
            float iv = sm[INVP_ + n0 + r];
            float2 lo = upk2(acl[r]), hi = upk2(ach[r]);
            float4 e;
            e.x = fmaf(lo.x, iv, bias.x);
            e.y = fmaf(lo.y, iv, bias.y);
            e.z = fmaf(hi.x, iv, bias.z);
            e.w = fmaf(hi.y, iv, bias.w);
            *(float4*)&gout[((n0 + r) << 6) + c0] = e;
        }
    }
}

__global__ __launch_bounds__(256, 3)
void gat_kernel(const float* __restrict__ x,
                const int* __restrict__ fhi,
                const float* __restrict__ w0,
                const float* __restrict__ as0,
                const float* __restrict__ ad0,
                const float* __restrict__ b0,
                const float* __restrict__ w1,
                const float* __restrict__ as1,
                const float* __restrict__ ad1,
                const float* __restrict__ b1,
                float* __restrict__ out) {
    extern __shared__ float sm[];
    unsigned* smu = (unsigned*)sm;
    int b = blockIdx.x;
    int scene = b >> 3, t = b & 7;
    int tid = threadIdx.x;
    int lane = tid & 31;

    // ---- global loads (R4 verbatim) ----
    {
        const float4* xb = (const float4*)(x + (size_t)b * 4096);
        #pragma unroll
        for (int k = 0; k < 4; k++) {
            int i = tid + (k << 8);
            int n = i >> 4, chunk = i & 15;
            *(float4*)&sm[H_ + (n << 6) + (((chunk ^ (n >> 2)) & 15) << 2)] = xb[i];
        }
        if (tid < 64) {
            sm[MSK_ + tid] = (fhi[(scene << 6) + tid] <= t) ? 1.0f : 0.0f;
            sm[AV_ + tid]       = as0[tid];
            sm[AV_ + 64 + tid]  = ad0[tid];
            sm[AV_ + 128 + tid] = as1[tid];
            sm[AV_ + 192 + tid] = ad1[tid];
            sm[BIA_ + 16 + tid] = b1[tid];
            if (tid < 16) sm[BIA_ + tid] = b0[tid];
        }
        #pragma unroll
        for (int k = 0; k < 16; k++) {
            int i = tid + (k << 8);
            int f = i >> 6, c = i & 63;
            sm[RG_ + i] = w0[((c >> 4) << 10) + (f << 4) + (c & 15)];
        }
    }
    __syncthreads();

    // ================= layer 0 =================
    inorm(sm, tid);
    gemmW(sm, tid);
    __syncthreads();

    { // scores: s,d per (head, node); DV holds masked d; per-warp max
        int hh = tid >> 6, n = tid & 63, a = n >> 2;
        float s = 0.f, d = 0.f;
        #pragma unroll
        for (int j = 0; j < 4; j++) {
            int jj = (j + n) & 3;
            int chunk = (hh << 2) + jj;
            float4 v = *(const float4*)&sm[HP_ + (n << 6) + (((chunk ^ a) & 15) << 2)];
            float4 vs = *(const float4*)&sm[AV_ + (hh << 4) + (jj << 2)];
            float4 vd = *(const float4*)&sm[AV_ + 64 + (hh << 4) + (jj << 2)];
            s = fmaf(v.x, vs.x, fmaf(v.y, vs.y, fmaf(v.z, vs.z, fmaf(v.w, vs.w, s))));
            d = fmaf(v.x, vd.x, fmaf(v.y, vd.y, fmaf(v.z, vd.z, fmaf(v.w, vd.w, d))));
        }
        sm[SV_ + tid] = s;
        float dm = (sm[MSK_ + n] > 0.f) ? d : -3.0e38f;
        sm[DV_ + tid] = dm;
        float md = dm;
        #pragma unroll
        for (int off = 16; off > 0; off >>= 1)
            md = fmaxf(md, __shfl_xor_sync(0xffffffffu, md, off));
        if (lane == 0) sm[DMX_ + (tid >> 5)] = md;
    }
    __syncthreads();

    { // p-pass L0: thread = (head, row); MUFU exp; fp16 stores (R4 verbatim)
        int hh = tid >> 6, n = tid & 63;
        float sB = sm[SV_ + tid];
        float valid = sm[MSK_ + n];
        float dmx = fmaxf(sm[DMX_ + (hh << 1)], sm[DMX_ + (hh << 1) + 1]);
        float mxv = sB + dmx; mxv = fmaxf(mxv, 0.2f * mxv);
        float nml = -mxv * L2E;
        float psum = 0.f;
        unsigned* pb = smu + RG_ + hh * PHW + (n << 5);
        int nx = n & 15;
        const float* dvb = &sm[DV_ + (hh << 6)];
        #pragma unroll 4
        for (int c = 0; c < 16; c++) {
            float4 d4 = *(const float4*)&dvb[c << 2];
            float v, lr;
            float4 pv;
            v = sB + d4.x; lr = fmaxf(v, 0.2f * v); pv.x = ex2_(fmaf(lr, L2E, nml));
            v = sB + d4.y; lr = fmaxf(v, 0.2f * v); pv.y = ex2_(fmaf(lr, L2E, nml));
            v = sB + d4.z; lr = fmaxf(v, 0.2f * v); pv.z = ex2_(fmaf(lr, L2E, nml));
            v = sB + d4.w; lr = fmaxf(v, 0.2f * v); pv.w = ex2_(fmaf(lr, L2E, nml));
            if (valid <= 0.f) { pv.x = 1.f; pv.y = 1.f; pv.z = 1.f; pv.w = 1.f; }
            psum += (pv.x + pv.y) + (pv.z + pv.w);
            uint2 uu; uu.x = pk2(pv.x, pv.y); uu.y = pk2(pv.z, pv.w);
            *(uint2*)(pb + ((c ^ nx) << 1)) = uu;
        }
        sm[INVP_ + hh * 68 + n] = 1.0f / psum;
    }
    __syncthreads();

    aggregate(sm, smu, tid, 0, (float*)0);   // ELU(out0)+b0 -> H_
    __syncthreads();

    // load W1 (overwrites dead p region)
    #pragma unroll
    for (int k = 0; k < 16; k++) {
        int i = tid + (k << 8);
        sm[RG_ + i] = w1[i];
    }
    __syncthreads();

    // ================= layer 1 =================
    inorm(sm, tid);
    gemmW(sm, tid);
    __syncthreads();

    { // scores L1: seg-split partial dots
        int row = tid & 63, seg = tid >> 6, a = row >> 2;
        float s = 0.f, d = 0.f;
        #pragma unroll
        for (int j = 0; j < 4; j++) {
            int jj = (j + row) & 3;
            int chunk = (seg << 2) + jj;
            float4 v = *(const float4*)&sm[HP_ + (row << 6) + (((chunk ^ a) & 15) << 2)];
            float4 vs = *(const float4*)&sm[AV_ + 128 + (seg << 4) + (jj << 2)];
            float4 vd = *(const float4*)&sm[AV_ + 192 + (seg << 4) + (jj << 2)];
            s = fmaf(v.x, vs.x, fmaf(v.y, vs.y, fmaf(v.z, vs.z, fmaf(v.w, vs.w, s))));
            d = fmaf(v.x, vd.x, fmaf(v.y, vd.y, fmaf(v.z, vd.z, fmaf(v.w, vd.w, d))));
        }
        sm[RED_ + tid] = s;
        sm[RED_ + 256 + tid] = d;
    }
    __syncthreads();
    if (tid < 64) {
        float s = sm[RED_ + tid] + sm[RED_ + 64 + tid] + sm[RED_ + 128 + tid] + sm[RED_ + 192 + tid];
        float d = sm[RED_ + 256 + tid] + sm[RED_ + 320 + tid] + sm[RED_ + 384 + tid] + sm[RED_ + 448 + tid];
        sm[SV_ + tid] = s;
        float dm = (sm[MSK_ + tid] > 0.f) ? d : -3.0e38f;
        sm[DV_ + tid] = dm;
        float md = dm;
        #pragma unroll
        for (int off = 16; off > 0; off >>= 1)
            md = fmaxf(md, __shfl_xor_sync(0xffffffffu, md, off));
        if (lane == 0) sm[DMX_ + 8 + (tid >> 5)] = md;
    }
    __syncthreads();

    { // p-pass L1: thread = (row, 16-m segment); fp16 stores (R4 verbatim)
        int row = tid & 63, seg = tid >> 6;
        float sB = sm[SV_ + row];
        float valid = sm[MSK_ + row];
        float dmx = fmaxf(sm[DMX_ + 8], sm[DMX_ + 9]);
        float mxv = sB + dmx; mxv = fmaxf(mxv, 0.2f * mxv);
        float nml = -mxv * L2E;
        float psum = 0.f;
        unsigned* pb = smu + RG_ + (row << 5);
        int nx = row & 12;
        #pragma unroll
        for (int i = 0; i < 4; i++) {
            int jj = (i + row) & 3;
            int sg = (seg << 2) + jj;
            float4 d4 = *(const float4*)&sm[DV_ + (sg << 2)];
            float v, lr;
            float4 pv;
            v = sB + d4.x; lr = fmaxf(v, 0.2f * v); pv.x = ex2_(fmaf(lr, L2E, nml));
            v = sB + d4.y; lr = fmaxf(v, 0.2f * v); pv.y = ex2_(fmaf(lr, L2E, nml));
            v = sB + d4.z; lr = fmaxf(v, 0.2f * v); pv.z = ex2_(fmaf(lr, L2E, nml));
            v = sB + d4.w; lr = fmaxf(v, 0.2f * v); pv.w = ex2_(fmaf(lr, L2E, nml));
            if (valid <= 0.f) { pv.x = 1.f; pv.y = 1.f; pv.z = 1.f; pv.w = 1.f; }
            psum += (pv.x + pv.y) + (pv.z + pv.w);
            uint2 uu; uu.x = pk2(pv.x, pv.y); uu.y = pk2(pv.z, pv.w);
            *(uint2*)(pb + (((sg ^ nx) & 15) << 1)) = uu;
        }
        sm[RED_ + tid] = psum;
    }
    __syncthreads();
    if (tid < 64)
        sm[INVP_ + tid] = 1.0f / (sm[RED_ + tid] + sm[RED_ + 64 + tid] +
                                  sm[RED_ + 128 + tid] + sm[RED_ + 192 + tid]);
    __syncthreads();

    aggregate(sm, smu, tid, 1, out + (size_t)b * 4096);
}

extern "C" void kernel_launch(void* const* d_in, const int* in_sizes, int n_in,
                              void* d_out, int out_size) {
    const float* x   = (const float*)d_in[0];
    const int*   fhi = (const int*)d_in[1];
    const float* w0  = (const float*)d_in[2];
    const float* as0 = (const float*)d_in[3];
    const float* ad0 = (const float*)d_in[4];
    const float* b0  = (const float*)d_in[5];
    const float* w1  = (const float*)d_in[6];
    const float* as1 = (const float*)d_in[7];
    const float* ad1 = (const float*)d_in[8];
    const float* b1  = (const float*)d_in[9];
    float* out = (float*)d_out;

    const int smem = SMF * 4;   // 73088 bytes
    cudaFuncSetAttribute(gat_kernel, cudaFuncAttributeMaxDynamicSharedMemorySize, smem);
    gat_kernel<<<8192, 256, smem>>>(x, fhi, w0, as0, ad0, b0, w1, as1, ad1, b1, out);
}